// round 14
// baseline (speedup 1.0000x reference)
#include <cuda_runtime.h>
#include <cuda_fp16.h>
#include <cstdint>

// ---------------------------------------------------------------------------
// ConstrainedEnhancementModel on GB300 (ptxas target sm_103: no 'a' features).
// R14 = R13 with gemm6 re-tiled per ncu evidence (l1tex=76% binding):
//   CTA 256x128, 512 threads, 16 warps (4M x 4N, warp 64x32), 1 CTA/SM.
//   Halves B LDG + B STS traffic per output tile (42 -> 36.5 KB L1/kt-equiv)
//   and halves w6 DRAM reads. fused_pre (L1..L5 persistent) unchanged.
// ---------------------------------------------------------------------------

#define NB   512
#define NL   256
#define NF   32
#define NH   4096
#define NOUTCOL (NH * NF)          // 131072
#define LAST_KNOT ((NL - 1) * 16)  // 4080
#define NBLK 128                   // persistent grid size

__device__ float  g_h1[512 * 1024];
__device__ float  g_h2[512 * 512];
__device__ float  g_fe[512 * 256];
__device__ float  g_d1[512 * 512];
__device__ __half g_d2h[512 * 1024];                // tiled [kt][m][16]

// grid barrier state (generation-based; survives graph replays)
__device__ volatile unsigned g_bar_gen;
__device__ unsigned g_bar_cnt;

__device__ __forceinline__ void grid_sync() {
    __syncthreads();
    if (threadIdx.x == 0) {
        const unsigned gen = g_bar_gen;
        __threadfence();
        const unsigned t = atomicAdd(&g_bar_cnt, 1);
        if (t == NBLK - 1) {
            g_bar_cnt = 0;
            __threadfence();
            g_bar_gen = gen + 1;
        } else {
            while (g_bar_gen == gen) { }
            __threadfence();
        }
    }
    __syncthreads();
}

// ===========================================================================
// helpers
// ===========================================================================
__device__ __forceinline__ uint32_t smem_u32(const void* p) {
    uint32_t a;
    asm("{ .reg .u64 t; cvta.to.shared.u64 t, %1; cvt.u32.u64 %0, t; }"
        : "=r"(a) : "l"(p));
    return a;
}
__device__ __forceinline__ void cp16_cg(uint32_t dst, const void* src) {
    asm volatile("cp.async.cg.shared.global [%0], [%1], 16;"
                 :: "r"(dst), "l"(src) : "memory");
}
#define CP_COMMIT() asm volatile("cp.async.commit_group;" ::: "memory")
#define CP_WAIT4()  asm volatile("cp.async.wait_group 4;" ::: "memory")

__device__ __forceinline__ void ldsm_x4(uint32_t& r0, uint32_t& r1,
                                        uint32_t& r2, uint32_t& r3, uint32_t addr) {
    asm volatile("ldmatrix.sync.aligned.m8n8.x4.shared.b16 {%0,%1,%2,%3}, [%4];"
                 : "=r"(r0), "=r"(r1), "=r"(r2), "=r"(r3) : "r"(addr));
}
__device__ __forceinline__ void ldsm_x4t(uint32_t& r0, uint32_t& r1,
                                         uint32_t& r2, uint32_t& r3, uint32_t addr) {
    asm volatile("ldmatrix.sync.aligned.m8n8.x4.trans.shared.b16 {%0,%1,%2,%3}, [%4];"
                 : "=r"(r0), "=r"(r1), "=r"(r2), "=r"(r3) : "r"(addr));
}

__device__ __forceinline__ void mma_fp16(float& c0, float& c1, float& c2, float& c3,
                                         uint32_t a0, uint32_t a1, uint32_t a2, uint32_t a3,
                                         uint32_t b0, uint32_t b1) {
    asm volatile(
        "mma.sync.aligned.m16n8k16.row.col.f32.f16.f16.f32 "
        "{%0,%1,%2,%3}, {%4,%5,%6,%7}, {%8,%9}, {%0,%1,%2,%3};"
        : "+f"(c0), "+f"(c1), "+f"(c2), "+f"(c3)
        : "r"(a0), "r"(a1), "r"(a2), "r"(a3), "r"(b0), "r"(b1));
}

__device__ __forceinline__ void sts_cvt4(uint32_t addr, float4 v) {
    __half2 h01 = __floats2half2_rn(v.x, v.y);
    __half2 h23 = __floats2half2_rn(v.z, v.w);
    uint32_t u0 = *reinterpret_cast<uint32_t*>(&h01);
    uint32_t u1 = *reinterpret_cast<uint32_t*>(&h23);
    asm volatile("st.shared.v2.b32 [%0], {%1,%2};"
                 :: "r"(addr), "r"(u0), "r"(u1) : "memory");
}

// ===========================================================================
// Phase bodies (device functions over a shared scratch buffer) — R13-identical
// ===========================================================================
#define L1_APITCH 40
#define L1_BPITCH 72
#define L1_ABUFH  (64 * L1_APITCH)
#define L1_BBUFH  (32 * L1_BPITCH)

__device__ void l1_phase(const float* __restrict__ low,
                         const float* __restrict__ w1,
                         const float* __restrict__ b1,
                         float* __restrict__ h1,
                         char* smbuf, int bid)
{
    __half* As = reinterpret_cast<__half*>(smbuf);
    __half* Bs = reinterpret_cast<__half*>(smbuf + 2 * L1_ABUFH * 2);

    const int tid  = threadIdx.x;
    const int wid  = tid >> 5;
    const int lane = tid & 31;
    const int g    = lane >> 2;
    const int q    = lane & 3;

    const int bm = (bid >> 4) * 64;
    const int bn = (bid & 15) * 64;

    const int wm = (wid >> 2) * 32;
    const int wn = (wid & 3) * 16;

    const uint32_t aBase = smem_u32(As);
    const uint32_t bBase = smem_u32(Bs);

    const int am0 = tid >> 3,  akc = tid & 7;
    const int bk0 = tid >> 4,  bnc = tid & 15;
    const float* aS = low + (size_t)(bm + am0) * 8192 + akc * 4;
    const float* bS = w1 + (size_t)bk0 * 1024 + bn + bnc * 4;
    const uint32_t aD0 = aBase + (uint32_t)(am0 * L1_APITCH + akc * 4) * 2;
    const uint32_t aD1 = aBase + (uint32_t)((am0 + 32) * L1_APITCH + akc * 4) * 2;
    const uint32_t bD0 = bBase + (uint32_t)(bk0 * L1_BPITCH + bnc * 4) * 2;
    const uint32_t bD1 = bBase + (uint32_t)((bk0 + 16) * L1_BPITCH + bnc * 4) * 2;

    float4 rA[2][2], rB[2][2];
#define L1_LDG(slot, it)                                                       \
    do {                                                                       \
        rA[slot][0] = *reinterpret_cast<const float4*>(aS + (it) * 32);        \
        rA[slot][1] = *reinterpret_cast<const float4*>(aS + 32 * 8192 + (it) * 32); \
        rB[slot][0] = *reinterpret_cast<const float4*>(bS + (size_t)(it) * 32 * 1024); \
        rB[slot][1] = *reinterpret_cast<const float4*>(bS + (size_t)((it) * 32 + 16) * 1024); \
    } while (0)

    L1_LDG(0, 0);
    L1_LDG(1, 1);

    const int mi = lane >> 3;
    const int r8 = lane & 7;
    const uint32_t aLd = aBase +
        (uint32_t)(((wm + (mi & 1) * 8 + r8) * L1_APITCH + (mi >> 1) * 8) * 2);
    const uint32_t bLd = bBase +
        (uint32_t)(((lane & 15) * L1_BPITCH + wn + (lane >> 4) * 8) * 2);

    float acc[2][2][4];
#pragma unroll
    for (int i = 0; i < 2; i++)
#pragma unroll
        for (int j = 0; j < 2; j++)
#pragma unroll
            for (int k = 0; k < 4; k++) acc[i][j][k] = 0.0f;

    for (int it = 0; it < 256; it++) {
        const int sl = it & 1;
        const uint32_t aOfs = (uint32_t)sl * (L1_ABUFH * 2);
        const uint32_t bOfs = (uint32_t)sl * (L1_BBUFH * 2);

        sts_cvt4(aD0 + aOfs, rA[sl][0]);
        sts_cvt4(aD1 + aOfs, rA[sl][1]);
        sts_cvt4(bD0 + bOfs, rB[sl][0]);
        sts_cvt4(bD1 + bOfs, rB[sl][1]);
        __syncthreads();

        if (it + 2 < 256) {
            L1_LDG(sl, it + 2);
        }

#pragma unroll
        for (int h = 0; h < 2; h++) {
            uint32_t b0, b1r, b2, b3;
            ldsm_x4t(b0, b1r, b2, b3,
                     bLd + bOfs + (uint32_t)(h * 16 * L1_BPITCH * 2));
#pragma unroll
            for (int mt = 0; mt < 2; mt++) {
                uint32_t a0, a1, a2, a3;
                ldsm_x4(a0, a1, a2, a3,
                        aLd + aOfs +
                        (uint32_t)((mt * 16 * L1_APITCH + h * 16) * 2));
                mma_fp16(acc[mt][0][0], acc[mt][0][1], acc[mt][0][2], acc[mt][0][3],
                         a0, a1, a2, a3, b0, b1r);
                mma_fp16(acc[mt][1][0], acc[mt][1][1], acc[mt][1][2], acc[mt][1][3],
                         a0, a1, a2, a3, b2, b3);
            }
        }
        __syncthreads();
    }
#undef L1_LDG

#pragma unroll
    for (int mt = 0; mt < 2; mt++) {
#pragma unroll
        for (int h8 = 0; h8 < 2; h8++) {
            const int row = bm + wm + mt * 16 + g + h8 * 8;
#pragma unroll
            for (int nt = 0; nt < 2; nt++) {
                const int col = bn + wn + nt * 8 + 2 * q;
                float v0 = fmaxf(acc[mt][nt][2 * h8]     + b1[col],     0.0f);
                float v1 = fmaxf(acc[mt][nt][2 * h8 + 1] + b1[col + 1], 0.0f);
                *reinterpret_cast<float2*>(h1 + (size_t)row * 1024 + col) =
                    make_float2(v0, v1);
            }
        }
    }
}

template <int BM, int BN, int BK, int TM, int TN, bool RELU, bool TILEDH>
__device__ void sgemm_phase(const float* __restrict__ A,
                            const float* __restrict__ Bm,
                            const float* __restrict__ bias,
                            void* __restrict__ Cv,
                            int M, int N, int K, char* smbuf, int bid)
{
    constexpr int THREADS = 256;
    float (*As)[BM + 4] = reinterpret_cast<float(*)[BM + 4]>(smbuf);
    float (*Bs)[BN] = reinterpret_cast<float(*)[BN]>(smbuf + BK * (BM + 4) * 4);

    const int tid = threadIdx.x;
    const int gw  = N / BN;
    const int bn  = (bid % gw) * BN;
    const int bm  = (bid / gw) * BM;
    const int tx  = tid % (BN / TN);
    const int ty  = tid / (BN / TN);

    float acc[TM][TN];
#pragma unroll
    for (int i = 0; i < TM; i++)
#pragma unroll
        for (int j = 0; j < TN; j++) acc[i][j] = 0.0f;

    constexpr int AV = BK / 4, AT = BM * AV;
    constexpr int BV = BN / 4, BT = BK * BV;

    for (int k0 = 0; k0 < K; k0 += BK) {
        for (int i = tid; i < AT; i += THREADS) {
            int r = i / AV, c4 = (i % AV) * 4;
            float4 v = *reinterpret_cast<const float4*>(
                A + (size_t)(bm + r) * K + k0 + c4);
            As[c4 + 0][r] = v.x; As[c4 + 1][r] = v.y;
            As[c4 + 2][r] = v.z; As[c4 + 3][r] = v.w;
        }
        for (int i = tid; i < BT; i += THREADS) {
            int r = i / BV, c4 = (i % BV) * 4;
            *reinterpret_cast<float4*>(&Bs[r][c4]) =
                *reinterpret_cast<const float4*>(
                    Bm + (size_t)(k0 + r) * N + bn + c4);
        }
        __syncthreads();

#pragma unroll
        for (int kk = 0; kk < BK; kk++) {
            float ra[TM], rb[TN];
            if constexpr (TM % 4 == 0) {
#pragma unroll
                for (int i = 0; i < TM; i += 4)
                    *reinterpret_cast<float4*>(&ra[i]) =
                        *reinterpret_cast<const float4*>(&As[kk][ty * TM + i]);
            } else {
#pragma unroll
                for (int i = 0; i < TM; i += 2)
                    *reinterpret_cast<float2*>(&ra[i]) =
                        *reinterpret_cast<const float2*>(&As[kk][ty * TM + i]);
            }
            if constexpr (TN % 4 == 0) {
#pragma unroll
                for (int j = 0; j < TN; j += 4)
                    *reinterpret_cast<float4*>(&rb[j]) =
                        *reinterpret_cast<const float4*>(&Bs[kk][tx * TN + j]);
            } else {
#pragma unroll
                for (int j = 0; j < TN; j += 2)
                    *reinterpret_cast<float2*>(&rb[j]) =
                        *reinterpret_cast<const float2*>(&Bs[kk][tx * TN + j]);
            }
#pragma unroll
            for (int i = 0; i < TM; i++)
#pragma unroll
                for (int j = 0; j < TN; j++)
                    acc[i][j] = fmaf(ra[i], rb[j], acc[i][j]);
        }
        __syncthreads();
    }

#pragma unroll
    for (int i = 0; i < TM; i++) {
        int row = bm + ty * TM + i;
#pragma unroll
        for (int j = 0; j < TN; j += 2) {
            int col = bn + tx * TN + j;
            float v0 = acc[i][j + 0] + bias[col + 0];
            float v1 = acc[i][j + 1] + bias[col + 1];
            if (RELU) {
                v0 = fmaxf(v0, 0.0f);
                v1 = fmaxf(v1, 0.0f);
            }
            if (TILEDH) {
                __half* C = (__half*)Cv;
                __half* p = C + ((size_t)(col >> 4) * M + row) * 16 + (col & 15);
                *reinterpret_cast<__half2*>(p) = __floats2half2_rn(v0, v1);
            } else {
                float* C = (float*)Cv;
                *reinterpret_cast<float2*>(C + (size_t)row * N + col) =
                    make_float2(v0, v1);
            }
        }
    }
}

__global__ void __launch_bounds__(256)
fused_pre(const float* __restrict__ low,
          const float* __restrict__ w1, const float* __restrict__ b1,
          const float* __restrict__ w2, const float* __restrict__ b2,
          const float* __restrict__ w3, const float* __restrict__ b3,
          const float* __restrict__ w4, const float* __restrict__ b4,
          const float* __restrict__ w5, const float* __restrict__ b5,
          float* __restrict__ h1, float* __restrict__ h2,
          float* __restrict__ fe, float* __restrict__ d1,
          __half* __restrict__ d2h)
{
    __shared__ __align__(16) char smbuf[19456];
    const int bid = blockIdx.x;

    l1_phase(low, w1, b1, h1, smbuf, bid);
    grid_sync();
    sgemm_phase<64, 32, 16, 4, 2, true, false>(h1, w2, b2, h2, 512, 512, 1024,
                                               smbuf, bid);
    grid_sync();
    sgemm_phase<32, 32, 16, 2, 2, false, false>(h2, w3, b3, fe, 512, 256, 512,
                                                smbuf, bid);
    grid_sync();
    sgemm_phase<64, 32, 16, 4, 2, true, false>(fe, w4, b4, d1, 512, 512, 256,
                                               smbuf, bid);
    grid_sync();
    sgemm_phase<64, 64, 16, 4, 4, true, true>(d1, w5, b5, d2h, 512, 1024, 512,
                                              smbuf, bid);
}

// ===========================================================================
// GEMM6 fp16: CTA 256x128, 512 threads, 16 warps (4M x 4N, warp 64x32).
// A: cp.async 6 stages dist 5 (12KB/stage). B: inline fp32->fp16, one
// float4/thread/kt, reg prefetch dist 2. ldmatrix frags; fused epilogue.
// ===========================================================================
#define G6_THREADS 512
#define G6_PITCH  24
#define G6_STG    6
#define G6_ATILEH (256 * G6_PITCH)         // 6144 halfs per A stage
#define G6_ATILEB (G6_ATILEH * 2)          // 12288 B
#define G6_BPITCH 136
#define G6_BBUFH  (16 * G6_BPITCH)         // 2176 halfs
#define G6_BBUFB  (G6_BBUFH * 2)           // 4352 B
#define G6_NKT    64
#define G6_SMEMB  (G6_STG * G6_ATILEB + 2 * G6_BBUFB + 512)   // 83 KB

__global__ void __launch_bounds__(G6_THREADS, 1)
gemm6_fp16(const __half* __restrict__ Ah,   // d2h tiled [64][512][16]
           const float* __restrict__ w6,    // fp32 [1024][131072]
           const float* __restrict__ bias,
           const float* __restrict__ low,
           float* __restrict__ out)
{
    extern __shared__ __half sm[];
    __half* Asm = sm;
    __half* Bsm = sm + G6_STG * G6_ATILEH;
    float*  sbias = reinterpret_cast<float*>(sm + G6_STG * G6_ATILEH + 2 * G6_BBUFH);

    const int tid  = threadIdx.x;
    const int wid  = tid >> 5;      // 0..15
    const int lane = tid & 31;
    const int g    = lane >> 2;
    const int q    = lane & 3;

    const int bm = blockIdx.x * 256;   // 2 M-blocks (fastest -> share w6 in L2)
    const int bn = blockIdx.y * 128;

    const int wm = (wid >> 2) * 64;    // 0..192
    const int wn = (wid & 3) * 32;     // 0..96

    if (tid < 128) sbias[tid] = bias[bn + tid];

    const uint32_t aBase = smem_u32(Asm);
    const uint32_t bBase = smem_u32(Bsm);

    // ---- A: cp.async; 512 threads cover 256 rows x 2 chunks ----
    const __half* aSrc = Ah + (size_t)bm * 16 + tid * 8;   // +8192 halfs per kt
    const uint32_t aDst = aBase + (tid >> 1) * 48 + (tid & 1) * 16;
#define G6_LOADA(s, kt) cp16_cg(aDst + (s) * G6_ATILEB, aSrc + (kt) * 8192)

    G6_LOADA(0, 0); CP_COMMIT();
    G6_LOADA(1, 1); CP_COMMIT();
    G6_LOADA(2, 2); CP_COMMIT();
    G6_LOADA(3, 3); CP_COMMIT();
    G6_LOADA(4, 4); CP_COMMIT();

    // ---- B: one float4 per thread per kt (16k x 128n fp32 tile) ----
    const int bk0 = tid >> 5;          // 0..15
    const int bnc = tid & 31;          // n-chunk
    const float* bS = w6 + (size_t)bk0 * NOUTCOL + bn + bnc * 4;
    const uint32_t bD = bBase + (uint32_t)(bk0 * G6_BPITCH + bnc * 4) * 2;

    float4 rb[2];
#define G6_LDGB(buf, kt) \
    rb[buf] = *reinterpret_cast<const float4*>(bS + (size_t)(kt) * 16 * NOUTCOL)

    G6_LDGB(0, 0);
    G6_LDGB(1, 1);

    const int mi = lane >> 3;
    const int r8 = lane & 7;
    const uint32_t aLd = aBase +
        (uint32_t)(((wm + (mi & 1) * 8 + r8) * G6_PITCH + (mi >> 1) * 8) * 2);
    const uint32_t bLd = bBase +
        (uint32_t)(((lane & 15) * G6_BPITCH + wn + (lane >> 4) * 8) * 2);

    float acc[4][4][4];
#pragma unroll
    for (int i = 0; i < 4; i++)
#pragma unroll
        for (int j = 0; j < 4; j++)
#pragma unroll
            for (int k = 0; k < 4; k++) acc[i][j][k] = 0.0f;

    int s = 0, sl = G6_STG - 1;
    for (int kt = 0; kt < G6_NKT; kt++) {
        const int buf = kt & 1;
        const uint32_t bOfs = (uint32_t)buf * G6_BBUFB;

        sts_cvt4(bD + bOfs, rb[buf]);

        if (kt + 2 < G6_NKT) {
            G6_LDGB(buf, kt + 2);
        }

        CP_WAIT4();
        __syncthreads();
        if (kt + 5 < G6_NKT) {
            G6_LOADA(sl, kt + 5);
        }
        CP_COMMIT();

        const uint32_t so = (uint32_t)s * G6_ATILEB;

        uint32_t bf[4][2];
        ldsm_x4t(bf[0][0], bf[0][1], bf[1][0], bf[1][1], bLd + bOfs);
        ldsm_x4t(bf[2][0], bf[2][1], bf[3][0], bf[3][1], bLd + bOfs + 32);

#pragma unroll
        for (int mt = 0; mt < 4; mt++) {
            uint32_t a0, a1, a2, a3;
            ldsm_x4(a0, a1, a2, a3, aLd + mt * (16 * G6_PITCH * 2) + so);
#pragma unroll
            for (int nt = 0; nt < 4; nt++)
                mma_fp16(acc[mt][nt][0], acc[mt][nt][1],
                         acc[mt][nt][2], acc[mt][nt][3],
                         a0, a1, a2, a3, bf[nt][0], bf[nt][1]);
        }

        s  = (s  + 1 == G6_STG) ? 0 : s  + 1;
        sl = (sl + 1 == G6_STG) ? 0 : sl + 1;
    }
#undef G6_LOADA
#undef G6_LDGB

    // ---- fused epilogue (warp-uniform t) ----
    const int t   = (bn + wn) >> 5;
    const int rem = t & 15;
    const int seg = t >> 4;
    const bool knot  = (rem == 0);
    const bool inseg = (!knot) && (t < LAST_KNOT);
    const float alpha = (float)rem * 0.0625f;
    const int segB = (seg < NL - 1) ? seg + 1 : NL - 1;

#pragma unroll
    for (int mt = 0; mt < 4; mt++) {
#pragma unroll
        for (int h = 0; h < 2; h++) {
            const int r = bm + wm + mt * 16 + g + h * 8;
            const float* lowr = low + (size_t)r * (NL * NF);
            float* outr = out + (size_t)r * NOUTCOL + bn + wn;
#pragma unroll
            for (int nt = 0; nt < 4; nt++) {
                const int f = nt * 8 + 2 * q;
                float dec0 = acc[mt][nt][2 * h]     + sbias[wn + f];
                float dec1 = acc[mt][nt][2 * h + 1] + sbias[wn + f + 1];
                float2 la = *reinterpret_cast<const float2*>(lowr + seg  * NF + f);
                float2 lb = *reinterpret_cast<const float2*>(lowr + segB * NF + f);
                float lin0 = (1.0f - alpha) * la.x + alpha * lb.x;
                float lin1 = (1.0f - alpha) * la.y + alpha * lb.y;
                float r0 = knot ? la.x : (inseg ? 0.8f * lin0 + 0.2f * dec0 : dec0);
                float r1 = knot ? la.y : (inseg ? 0.8f * lin1 + 0.2f * dec1 : dec1);
                *reinterpret_cast<float2*>(outr + f) = make_float2(r0, r1);
            }
        }
    }
}

// ---------------------------------------------------------------------------
extern "C" void kernel_launch(void* const* d_in, const int* in_sizes, int n_in,
                              void* d_out, int out_size)
{
    const float* low = (const float*)d_in[0];
    const float* w1  = (const float*)d_in[1];
    const float* b1  = (const float*)d_in[2];
    const float* w2  = (const float*)d_in[3];
    const float* b2  = (const float*)d_in[4];
    const float* w3  = (const float*)d_in[5];
    const float* b3  = (const float*)d_in[6];
    const float* w4  = (const float*)d_in[7];
    const float* b4  = (const float*)d_in[8];
    const float* w5  = (const float*)d_in[9];
    const float* b5  = (const float*)d_in[10];
    const float* w6  = (const float*)d_in[11];
    const float* b6  = (const float*)d_in[12];
    float* out = (float*)d_out;

    float  *h1, *h2, *fe, *d1;
    __half *d2h;
    cudaGetSymbolAddress((void**)&h1,  g_h1);
    cudaGetSymbolAddress((void**)&h2,  g_h2);
    cudaGetSymbolAddress((void**)&fe,  g_fe);
    cudaGetSymbolAddress((void**)&d1,  g_d1);
    cudaGetSymbolAddress((void**)&d2h, g_d2h);

    cudaFuncSetAttribute(gemm6_fp16,
                         cudaFuncAttributeMaxDynamicSharedMemorySize, G6_SMEMB);

    // Launch 1: fused L1..L5 (persistent 128 CTAs, grid_sync between phases)
    fused_pre<<<NBLK, 256>>>(low, w1, b1, w2, b2, w3, b3, w4, b4, w5, b5,
                             h1, h2, fe, d1, d2h);
    // Launch 2: GEMM6 (CTA 256x128, grid 2 x 1024)
    gemm6_fp16<<<dim3(2, NOUTCOL / 128), G6_THREADS, G6_SMEMB>>>(
        d2h, w6, b6, low, out);
}